// round 1
// baseline (speedup 1.0000x reference)
#include <cuda_runtime.h>
#include <math.h>

#define NN  131072
#define GG  1024
#define NPG 128
#define EE  2097152
#define HH  64
#define KK  30
#define DD  193
#define CAP 3072

// ---------------- scratch (static device globals; no allocation) ----------------
__device__ int g_deg[NN];
__device__ int g_cur[NN];
__device__ int g_noff[NN + 1];
__device__ int g_gtot[GG];
__device__ int g_gbase[GG];
__device__ unsigned char g_esrc[EE];

// ---------------- preprocessing: build per-node CSR of in-edges ----------------
__global__ void k_zero() {
    int i = blockIdx.x * blockDim.x + threadIdx.x;
    if (i < NN) { g_deg[i] = 0; g_cur[i] = 0; }
}

__global__ void k_count(const int* __restrict__ dst) {
    int e = blockIdx.x * blockDim.x + threadIdx.x;
    if (e < EE) atomicAdd(&g_deg[dst[e]], 1);
}

__global__ void k_gtot() {
    int g = blockIdx.x, i = threadIdx.x;
    int v = g_deg[g * NPG + i];
    for (int o = 16; o; o >>= 1) v += __shfl_down_sync(0xffffffffu, v, o);
    __shared__ int ws[4];
    if ((i & 31) == 0) ws[i >> 5] = v;
    __syncthreads();
    if (i == 0) g_gtot[g] = ws[0] + ws[1] + ws[2] + ws[3];
}

__global__ void k_gscan() {
    __shared__ int s[GG];
    int t = threadIdx.x;
    int v = g_gtot[t];
    s[t] = v;
    __syncthreads();
    for (int o = 1; o < GG; o <<= 1) {
        int a = (t >= o) ? s[t - o] : 0;
        __syncthreads();
        s[t] += a;
        __syncthreads();
    }
    g_gbase[t] = s[t] - v;
    if (t == 0) g_noff[NN] = EE;
}

__global__ void k_noff() {
    int g = blockIdx.x, i = threadIdx.x;
    int lane = i & 31, w = i >> 5;
    int v = g_deg[g * NPG + i];
    int x = v;
    for (int o = 1; o < 32; o <<= 1) {
        int t = __shfl_up_sync(0xffffffffu, x, o);
        if (lane >= o) x += t;
    }
    __shared__ int ws[4], wb[4];
    if (lane == 31) ws[w] = x;
    __syncthreads();
    if (i == 0) { int a = 0; for (int q = 0; q < 4; q++) { wb[q] = a; a += ws[q]; } }
    __syncthreads();
    g_noff[g * NPG + i] = g_gbase[g] + wb[w] + x - v;  // exclusive offset
}

__global__ void k_scatter(const int* __restrict__ src, const int* __restrict__ dst) {
    int e = blockIdx.x * blockDim.x + threadIdx.x;
    if (e < EE) {
        int d = dst[e];
        int pos = g_noff[d] + atomicAdd(&g_cur[d], 1);
        g_esrc[pos] = (unsigned char)(src[e] & 127);
    }
}

// ---------------- main fused per-graph kernel ----------------
struct SmemD {
    float xc[NPG * 197];   // concat(x1,x2,x3,x4) node-major, stride 197 (odd)
    float h2t[64 * 129];   // h * dinv[src], CHANNEL-major, stride 129 (odd)
    float x0[NPG * 65];    // embedding, stride 65 (odd)
    float Wsh[4096];       // weight staging (reused for conv1_w / conv2_w)
    float dinv[NPG];
    float keyv[NPG];
    float bsh[64];         // bias (or W3)
    float h4t[NPG];
    float partial[256];
    float h1c[16 * KK];
    float pool[16 * 16];
    float c2o[352];
    float hm[128];
    int   noff[NPG + 1];
    int   sel[KK];
    unsigned char esrc[CAP];
};

__global__ __launch_bounds__(256, 1) void k_main(
    const int* __restrict__ z, const float* __restrict__ z_table,
    const float* __restrict__ W0, const float* __restrict__ b0,
    const float* __restrict__ W1, const float* __restrict__ b1,
    const float* __restrict__ W2, const float* __restrict__ b2,
    const float* __restrict__ W3, const float* __restrict__ b3,
    const float* __restrict__ c1w, const float* __restrict__ c1b,
    const float* __restrict__ c2w, const float* __restrict__ c2b,
    const float* __restrict__ l1w, const float* __restrict__ l1b,
    const float* __restrict__ l2w, const float* __restrict__ l2b,
    float* __restrict__ out)
{
    extern __shared__ unsigned char smraw[];
    SmemD& s = *reinterpret_cast<SmemD*>(smraw);
    const int tid = threadIdx.x;
    const int g = blockIdx.x;
    const int nb = g * NPG;

    // ---- init: offsets, degrees, edge copy, embedding ----
    if (tid <= NPG) s.noff[tid] = g_noff[nb + tid];
    __syncthreads();
    const int base = s.noff[0];
    const int cnt = s.noff[NPG] - base;
    const bool inS = (cnt <= CAP);

    if (tid < NPG) {
        int dl = s.noff[tid + 1] - s.noff[tid];
        s.dinv[tid] = rsqrtf((float)(dl + 1));   // +1 self loop
    }
    if (inS) {
        for (int i = tid; i < cnt; i += 256) s.esrc[i] = g_esrc[base + i];
    }
    for (int idx = tid; idx < NPG * 64; idx += 256) {
        int n = idx >> 6, c = idx & 63;
        s.x0[n * 65 + c] = __ldg(&z_table[__ldg(&z[nb + n]) * 64 + c]);
    }
    __syncthreads();

    // ---- GEMM: h2t[c][r] = (xin @ W)[r][c] * dinv[r]  (8 rows x 4 cols / thread) ----
    auto gemm = [&](const float* xin, int sin, const float* Wg) {
        for (int i = tid; i < 4096; i += 256) s.Wsh[i] = Wg[i];
        __syncthreads();
        const int cg = tid & 15;      // c = cg + 16*j  -> conflict-free W loads
        const int r0 = (tid >> 4) * 8;
        float acc[8][4];
        #pragma unroll
        for (int i = 0; i < 8; i++)
            #pragma unroll
            for (int j = 0; j < 4; j++) acc[i][j] = 0.f;
        #pragma unroll 4
        for (int k = 0; k < 64; k++) {
            float wv[4];
            #pragma unroll
            for (int j = 0; j < 4; j++) wv[j] = s.Wsh[k * 64 + cg + 16 * j];
            #pragma unroll
            for (int i = 0; i < 8; i++) {
                float xv = xin[(r0 + i) * sin + k];
                #pragma unroll
                for (int j = 0; j < 4; j++) acc[i][j] += xv * wv[j];
            }
        }
        #pragma unroll
        for (int i = 0; i < 8; i++) {
            float dv = s.dinv[r0 + i];
            #pragma unroll
            for (int j = 0; j < 4; j++)
                s.h2t[(cg + 16 * j) * 129 + r0 + i] = acc[i][j] * dv;
        }
        __syncthreads();
    };

    // ---- gather + tanh: xc[d][outbase+c] = tanh(dinv[d]*(h2t[c][d] + sum_in h2t[c][s]) + b[c]) ----
    auto gather = [&](int outbase) {
        const int c = tid & 63;
        const int dg = tid >> 6;
        const float* hr = &s.h2t[c * 129];
        const float bc = s.bsh[c];
        for (int dd = 0; dd < 32; dd++) {
            int d = dg * 32 + dd;
            float sum = hr[d];                      // self loop
            int e0 = s.noff[d] - base, e1 = s.noff[d + 1] - base;
            if (inS) {
                for (int e = e0; e < e1; e++) sum += hr[s.esrc[e]];
            } else {
                for (int e = e0; e < e1; e++) sum += hr[g_esrc[base + e]];
            }
            s.xc[d * 197 + outbase + c] = tanhf(s.dinv[d] * sum + bc);
        }
        __syncthreads();
    };

    if (tid < 64) s.bsh[tid] = b0[tid];
    gemm(s.x0, 65, W0);        gather(0);
    if (tid < 64) s.bsh[tid] = b1[tid];
    gemm(&s.xc[0], 197, W1);   gather(64);
    if (tid < 64) s.bsh[tid] = b2[tid];
    gemm(&s.xc[64], 197, W2);  gather(128);

    // ---- layer 4: 64 -> 1 ----
    if (tid < 64) s.bsh[tid] = W3[tid];
    __syncthreads();
    if (tid < 128) {
        float sum = 0.f;
        #pragma unroll 8
        for (int k = 0; k < 64; k++) sum += s.xc[tid * 197 + 128 + k] * s.bsh[k];
        s.h4t[tid] = sum * s.dinv[tid];
    }
    __syncthreads();
    if (tid < 128) {
        int d = tid;
        float sum = s.h4t[d];
        int e0 = s.noff[d] - base, e1 = s.noff[d + 1] - base;
        if (inS) {
            for (int e = e0; e < e1; e++) sum += s.h4t[s.esrc[e]];
        } else {
            for (int e = e0; e < e1; e++) sum += s.h4t[g_esrc[base + e]];
        }
        float v = tanhf(s.dinv[d] * sum + b3[0]);
        s.keyv[d] = v;
        s.xc[d * 197 + 192] = v;
    }
    __syncthreads();

    // ---- sort-pool: stable descending rank of keyv; keep top KK ----
    if (tid < 128) {
        float ki = s.keyv[tid];
        int r = 0;
        for (int j = 0; j < 128; j++) {
            float kj = s.keyv[j];
            r += (kj > ki) || (kj == ki && j < tid);
        }
        if (r < KK) s.sel[r] = tid;
    }
    __syncthreads();

    // ---- conv1: per-node linear D->16, relu ----
    for (int i = tid; i < 16 * DD; i += 256) s.Wsh[i] = c1w[i];
    __syncthreads();
    for (int idx = tid; idx < 16 * KK; idx += 256) {
        int c = idx & 15, k2 = idx >> 4;
        const float* row = &s.xc[s.sel[k2] * 197];
        const float* wr = &s.Wsh[c * DD];
        float sum = __ldg(&c1b[c]);
        for (int d2 = 0; d2 < DD; d2++) sum += row[d2] * wr[d2];
        s.h1c[c * KK + k2] = fmaxf(sum, 0.f);
    }
    __syncthreads();

    // ---- maxpool(2,2) + stage conv2_w ----
    if (tid < 240) {
        int c = tid / 15, t2 = tid % 15;
        s.pool[c * 16 + t2] = fmaxf(s.h1c[c * KK + 2 * t2], s.h1c[c * KK + 2 * t2 + 1]);
    }
    for (int i = tid; i < 2560; i += 256) s.Wsh[i] = c2w[i];
    __syncthreads();

    // ---- conv2: 16ch x len15, k=5 -> 32ch x len11, relu; c2o IS the torch-order flatten ----
    for (int idx = tid; idx < 352; idx += 256) {
        int o = idx / 11, t2 = idx % 11;
        float sum = __ldg(&c2b[o]);
        const float* wr = &s.Wsh[o * 80];
        #pragma unroll
        for (int i3 = 0; i3 < 16; i3++)
            #pragma unroll
            for (int j3 = 0; j3 < 5; j3++)
                sum += s.pool[i3 * 16 + t2 + j3] * wr[i3 * 5 + j3];
        s.c2o[idx] = fmaxf(sum, 0.f);
    }
    __syncthreads();

    // ---- lin1 (352->128, relu), split f-range over 2 threads per output ----
    {
        int m = tid & 127, hf = tid >> 7;
        int f0 = hf * 176;
        float sum = 0.f;
        for (int f = f0; f < f0 + 176; f++) sum += s.c2o[f] * __ldg(&l1w[f * 128 + m]);
        s.partial[tid] = sum;
    }
    __syncthreads();
    if (tid < 128)
        s.hm[tid] = fmaxf(s.partial[tid] + s.partial[tid + 128] + __ldg(&l1b[tid]), 0.f);
    __syncthreads();

    // ---- lin2 (128->1) ----
    if (tid < 32) {
        float sum = 0.f;
        #pragma unroll
        for (int q = 0; q < 4; q++) {
            int m = tid + 32 * q;
            sum += s.hm[m] * __ldg(&l2w[m]);
        }
        for (int o = 16; o; o >>= 1) sum += __shfl_down_sync(0xffffffffu, sum, o);
        if (tid == 0) out[g] = sum + __ldg(&l2b[0]);
    }
}

// ---------------- launch ----------------
extern "C" void kernel_launch(void* const* d_in, const int* in_sizes, int n_in,
                              void* d_out, int out_size) {
    const int*   z   = (const int*)d_in[0];
    const int*   ei  = (const int*)d_in[1];
    const float* zt  = (const float*)d_in[3];
    const float* W0  = (const float*)d_in[4];
    const float* b0  = (const float*)d_in[5];
    const float* W1  = (const float*)d_in[6];
    const float* b1  = (const float*)d_in[7];
    const float* W2  = (const float*)d_in[8];
    const float* b2  = (const float*)d_in[9];
    const float* W3  = (const float*)d_in[10];
    const float* b3  = (const float*)d_in[11];
    const float* c1w = (const float*)d_in[12];
    const float* c1b = (const float*)d_in[13];
    const float* c2w = (const float*)d_in[14];
    const float* c2b = (const float*)d_in[15];
    const float* l1w = (const float*)d_in[16];
    const float* l1b = (const float*)d_in[17];
    const float* l2w = (const float*)d_in[18];
    const float* l2b = (const float*)d_in[19];
    float* out = (float*)d_out;

    const int* src = ei;
    const int* dst = ei + EE;

    k_zero<<<NN / 256, 256>>>();
    k_count<<<EE / 256, 256>>>(dst);
    k_gtot<<<GG, 128>>>();
    k_gscan<<<1, GG>>>();
    k_noff<<<GG, 128>>>();
    k_scatter<<<EE / 256, 256>>>(src, dst);

    static_assert(sizeof(SmemD) <= 232448, "smem too large");
    cudaFuncSetAttribute(k_main, cudaFuncAttributeMaxDynamicSharedMemorySize,
                         (int)sizeof(SmemD));
    k_main<<<GG, 256, sizeof(SmemD)>>>(z, zt, W0, b0, W1, b1, W2, b2, W3, b3,
                                       c1w, c1b, c2w, c2b, l1w, l1b, l2w, l2b, out);
}

// round 3
// speedup vs baseline: 1.4426x; 1.4426x over previous
#include <cuda_runtime.h>
#include <math.h>

#define NN  131072
#define GG  1024
#define NPG 128
#define EE  2097152
#define HH  64
#define KK  30
#define DD  193
#define CAP 3072
#define SXC 196   // xc row stride (multiple of 4)
#define SX0 68    // x0 row stride (multiple of 4)

// ---------------- scratch (static device globals; no allocation) ----------------
__device__ int g_deg[NN];
__device__ int g_cur[NN];
__device__ int g_noff[NN + 1];
__device__ int g_gtot[GG];
__device__ int g_gbase[GG];
__device__ unsigned char g_esrc[EE];

// ---------------- preprocessing: build per-node CSR of in-edges ----------------
__global__ void k_count(const int* __restrict__ dst) {
    int e = blockIdx.x * blockDim.x + threadIdx.x;
    if (e < EE) atomicAdd(&g_deg[dst[e]], 1);
}

__global__ void k_gtot() {
    int g = blockIdx.x, i = threadIdx.x;
    int v = g_deg[g * NPG + i];
    for (int o = 16; o; o >>= 1) v += __shfl_down_sync(0xffffffffu, v, o);
    __shared__ int ws[4];
    if ((i & 31) == 0) ws[i >> 5] = v;
    __syncthreads();
    if (i == 0) g_gtot[g] = ws[0] + ws[1] + ws[2] + ws[3];
}

__global__ void k_gscan() {
    __shared__ int s[GG];
    int t = threadIdx.x;
    int v = g_gtot[t];
    s[t] = v;
    __syncthreads();
    for (int o = 1; o < GG; o <<= 1) {
        int a = (t >= o) ? s[t - o] : 0;
        __syncthreads();
        s[t] += a;
        __syncthreads();
    }
    g_gbase[t] = s[t] - v;
    if (t == 0) g_noff[NN] = EE;
}

__global__ void k_noff() {
    int g = blockIdx.x, i = threadIdx.x;
    int lane = i & 31, w = i >> 5;
    int v = g_deg[g * NPG + i];
    int x = v;
    for (int o = 1; o < 32; o <<= 1) {
        int t = __shfl_up_sync(0xffffffffu, x, o);
        if (lane >= o) x += t;
    }
    __shared__ int ws[4], wb[4];
    if (lane == 31) ws[w] = x;
    __syncthreads();
    if (i == 0) { int a = 0; for (int q = 0; q < 4; q++) { wb[q] = a; a += ws[q]; } }
    __syncthreads();
    g_noff[g * NPG + i] = g_gbase[g] + wb[w] + x - v;  // exclusive offset
}

__global__ void k_scatter(const int* __restrict__ src, const int* __restrict__ dst) {
    int e = blockIdx.x * blockDim.x + threadIdx.x;
    if (e < EE) {
        int d = dst[e];
        int pos = g_noff[d] + atomicAdd(&g_cur[d], 1);
        g_esrc[pos] = (unsigned char)(src[e] & 127);
    }
}

// ---------------- main fused per-graph kernel ----------------
struct SmemD {
    float xc[NPG * SXC];   // concat(x1,x2,x3,x4) node-major, stride 196
    float h2t[64 * 129];   // h * dinv[src], CHANNEL-major, stride 129 (odd)
    float x0[NPG * SX0];   // embedding, stride 68
    float Wsh[4096];       // weight staging (reused for conv1_w / conv2_w)
    float dinv[NPG];
    float keyv[NPG];
    float bsh[64];         // bias (or W3)
    float h4t[NPG];
    float partial[512];
    float h1c[16 * KK];
    float pool[16 * 16];
    float c2o[352];
    float hm[128];
    int   noff[NPG + 1];
    int   sel[KK];
    unsigned char esrc[CAP];
};

__global__ __launch_bounds__(512, 1) void k_main(
    const int* __restrict__ z, const float* __restrict__ z_table,
    const float* __restrict__ W0, const float* __restrict__ b0,
    const float* __restrict__ W1, const float* __restrict__ b1,
    const float* __restrict__ W2, const float* __restrict__ b2,
    const float* __restrict__ W3, const float* __restrict__ b3,
    const float* __restrict__ c1w, const float* __restrict__ c1b,
    const float* __restrict__ c2w, const float* __restrict__ c2b,
    const float* __restrict__ l1w, const float* __restrict__ l1b,
    const float* __restrict__ l2w, const float* __restrict__ l2b,
    float* __restrict__ out)
{
    extern __shared__ unsigned char smraw[];
    SmemD& s = *reinterpret_cast<SmemD*>(smraw);
    const int tid = threadIdx.x;
    const int g = blockIdx.x;
    const int nb = g * NPG;

    // ---- init: offsets, degrees, edge copy, embedding ----
    if (tid <= NPG) s.noff[tid] = g_noff[nb + tid];
    __syncthreads();
    const int base = s.noff[0];
    const int cnt = s.noff[NPG] - base;
    const bool inS = (cnt <= CAP);

    if (tid < NPG) {
        int dl = s.noff[tid + 1] - s.noff[tid];
        s.dinv[tid] = rsqrtf((float)(dl + 1));   // +1 self loop
    }
    if (inS) {
        for (int i = tid; i < cnt; i += 512) s.esrc[i] = g_esrc[base + i];
    }
    // embedding: float4 per item
    for (int idx = tid; idx < NPG * 16; idx += 512) {
        int n = idx >> 4, q = idx & 15;
        float4 v = *reinterpret_cast<const float4*>(&z_table[__ldg(&z[nb + n]) * 64 + 4 * q]);
        *reinterpret_cast<float4*>(&s.x0[n * SX0 + 4 * q]) = v;
    }
    __syncthreads();

    // ---- GEMM: h2t[c][r] = (xin @ W)[r][c] * dinv[r]  (4 rows x 4 cols / thread) ----
    auto gemm = [&](const float* xin, int sin, const float* Wg) {
        for (int i = tid; i < 1024; i += 512)
            *reinterpret_cast<float4*>(&s.Wsh[4 * i]) =
                *reinterpret_cast<const float4*>(&Wg[4 * i]);
        __syncthreads();
        const int c0 = (tid & 15) * 4;     // 4 contiguous cols
        const int r0 = (tid >> 4) * 4;     // 4 rows
        float acc[4][4];
        #pragma unroll
        for (int i = 0; i < 4; i++)
            #pragma unroll
            for (int j = 0; j < 4; j++) acc[i][j] = 0.f;
        #pragma unroll 4
        for (int kk = 0; kk < 16; kk++) {
            float4 xv[4];
            #pragma unroll
            for (int i = 0; i < 4; i++)
                xv[i] = *reinterpret_cast<const float4*>(&xin[(r0 + i) * sin + 4 * kk]);
            #pragma unroll
            for (int kq = 0; kq < 4; kq++) {
                float4 wv = *reinterpret_cast<const float4*>(&s.Wsh[(4 * kk + kq) * 64 + c0]);
                float xs[4] = { (&xv[0].x)[kq], (&xv[1].x)[kq], (&xv[2].x)[kq], (&xv[3].x)[kq] };
                #pragma unroll
                for (int i = 0; i < 4; i++) {
                    acc[i][0] += xs[i] * wv.x;
                    acc[i][1] += xs[i] * wv.y;
                    acc[i][2] += xs[i] * wv.z;
                    acc[i][3] += xs[i] * wv.w;
                }
            }
        }
        #pragma unroll
        for (int i = 0; i < 4; i++) {
            float dv = s.dinv[r0 + i];
            #pragma unroll
            for (int j = 0; j < 4; j++)
                s.h2t[(c0 + j) * 129 + r0 + i] = acc[i][j] * dv;
        }
        __syncthreads();
    };

    // ---- gather + tanh ----
    auto gather = [&](int outbase) {
        const int c = tid & 63;
        const int dg = tid >> 6;           // 0..7, 16 dst each
        const float* hr = &s.h2t[c * 129];
        const float bc = s.bsh[c];
        #pragma unroll 2
        for (int dd = 0; dd < 16; dd++) {
            int d = dg * 16 + dd;
            float sum = hr[d];                      // self loop
            int e0 = s.noff[d] - base, e1 = s.noff[d + 1] - base;
            int e = e0;
            if (inS) {
                for (; e + 4 <= e1; e += 4) {
                    int a0 = s.esrc[e], a1 = s.esrc[e + 1];
                    int a2 = s.esrc[e + 2], a3 = s.esrc[e + 3];
                    sum += hr[a0] + hr[a1] + hr[a2] + hr[a3];
                }
                for (; e < e1; e++) sum += hr[s.esrc[e]];
            } else {
                for (; e < e1; e++) sum += hr[g_esrc[base + e]];
            }
            s.xc[d * SXC + outbase + c] = tanhf(s.dinv[d] * sum + bc);
        }
        __syncthreads();
    };

    if (tid < 64) s.bsh[tid] = b0[tid];
    gemm(s.x0, SX0, W0);        gather(0);
    if (tid < 64) s.bsh[tid] = b1[tid];
    gemm(&s.xc[0], SXC, W1);    gather(64);
    if (tid < 64) s.bsh[tid] = b2[tid];
    gemm(&s.xc[64], SXC, W2);   gather(128);

    // ---- layer 4: 64 -> 1 ----
    if (tid < 64) s.bsh[tid] = W3[tid];
    __syncthreads();
    if (tid < 128) {
        float sum = 0.f;
        #pragma unroll
        for (int kq = 0; kq < 16; kq++) {
            float4 xv = *reinterpret_cast<const float4*>(&s.xc[tid * SXC + 128 + 4 * kq]);
            sum += xv.x * s.bsh[4 * kq] + xv.y * s.bsh[4 * kq + 1]
                 + xv.z * s.bsh[4 * kq + 2] + xv.w * s.bsh[4 * kq + 3];
        }
        s.h4t[tid] = sum * s.dinv[tid];
    }
    __syncthreads();
    if (tid < 128) {
        int d = tid;
        float sum = s.h4t[d];
        int e0 = s.noff[d] - base, e1 = s.noff[d + 1] - base;
        if (inS) {
            int e = e0;
            for (; e + 4 <= e1; e += 4) {
                int a0 = s.esrc[e], a1 = s.esrc[e + 1];
                int a2 = s.esrc[e + 2], a3 = s.esrc[e + 3];
                sum += s.h4t[a0] + s.h4t[a1] + s.h4t[a2] + s.h4t[a3];
            }
            for (; e < e1; e++) sum += s.h4t[s.esrc[e]];
        } else {
            for (int e = e0; e < e1; e++) sum += s.h4t[g_esrc[base + e]];
        }
        float v = tanhf(s.dinv[d] * sum + b3[0]);
        s.keyv[d] = v;
        s.xc[d * SXC + 192] = v;
    }
    __syncthreads();

    // ---- sort-pool: stable descending rank of keyv; keep top KK ----
    if (tid < 128) {
        float ki = s.keyv[tid];
        int r = 0;
        for (int j = 0; j < 128; j++) {
            float kj = s.keyv[j];
            r += (kj > ki) || (kj == ki && j < tid);
        }
        if (r < KK) s.sel[r] = tid;
    }
    __syncthreads();

    // ---- conv1: per-node linear D->16, relu ----
    for (int i = tid; i < 16 * DD; i += 512) s.Wsh[i] = c1w[i];
    __syncthreads();
    if (tid < 16 * KK) {
        int c = tid & 15, k2 = tid >> 4;
        const float* row = &s.xc[s.sel[k2] * SXC];
        const float* wr = &s.Wsh[c * DD];
        float sum = __ldg(&c1b[c]);
        for (int d2 = 0; d2 < DD; d2++) sum += row[d2] * wr[d2];
        s.h1c[c * KK + k2] = fmaxf(sum, 0.f);
    }
    __syncthreads();

    // ---- maxpool(2,2) + stage conv2_w ----
    if (tid < 240) {
        int c = tid / 15, t2 = tid % 15;
        s.pool[c * 16 + t2] = fmaxf(s.h1c[c * KK + 2 * t2], s.h1c[c * KK + 2 * t2 + 1]);
    }
    for (int i = tid; i < 2560; i += 512) s.Wsh[i] = c2w[i];
    __syncthreads();

    // ---- conv2: 16ch x len15, k=5 -> 32ch x len11, relu ----
    if (tid < 352) {
        int o = tid / 11, t2 = tid % 11;
        float sum = __ldg(&c2b[o]);
        const float* wr = &s.Wsh[o * 80];
        #pragma unroll
        for (int i3 = 0; i3 < 16; i3++)
            #pragma unroll
            for (int j3 = 0; j3 < 5; j3++)
                sum += s.pool[i3 * 16 + t2 + j3] * wr[i3 * 5 + j3];
        s.c2o[tid] = fmaxf(sum, 0.f);
    }
    __syncthreads();

    // ---- lin1 (352->128, relu), 4-way f-split ----
    {
        int m = tid & 127, q = tid >> 7;
        int f0 = q * 88;
        float sum = 0.f;
        for (int f = f0; f < f0 + 88; f++) sum += s.c2o[f] * __ldg(&l1w[f * 128 + m]);
        s.partial[tid] = sum;
    }
    __syncthreads();
    if (tid < 128)
        s.hm[tid] = fmaxf(s.partial[tid] + s.partial[tid + 128] + s.partial[tid + 256]
                          + s.partial[tid + 384] + __ldg(&l1b[tid]), 0.f);
    __syncthreads();

    // ---- lin2 (128->1) ----
    if (tid < 32) {
        float sum = 0.f;
        #pragma unroll
        for (int q = 0; q < 4; q++) {
            int m = tid + 32 * q;
            sum += s.hm[m] * __ldg(&l2w[m]);
        }
        for (int o = 16; o; o >>= 1) sum += __shfl_down_sync(0xffffffffu, sum, o);
        if (tid == 0) out[g] = sum + __ldg(&l2b[0]);
    }
}

// ---------------- launch ----------------
extern "C" void kernel_launch(void* const* d_in, const int* in_sizes, int n_in,
                              void* d_out, int out_size) {
    const int*   z   = (const int*)d_in[0];
    const int*   ei  = (const int*)d_in[1];
    const float* zt  = (const float*)d_in[3];
    const float* W0  = (const float*)d_in[4];
    const float* b0  = (const float*)d_in[5];
    const float* W1  = (const float*)d_in[6];
    const float* b1  = (const float*)d_in[7];
    const float* W2  = (const float*)d_in[8];
    const float* b2  = (const float*)d_in[9];
    const float* W3  = (const float*)d_in[10];
    const float* b3  = (const float*)d_in[11];
    const float* c1w = (const float*)d_in[12];
    const float* c1b = (const float*)d_in[13];
    const float* c2w = (const float*)d_in[14];
    const float* c2b = (const float*)d_in[15];
    const float* l1w = (const float*)d_in[16];
    const float* l1b = (const float*)d_in[17];
    const float* l2w = (const float*)d_in[18];
    const float* l2b = (const float*)d_in[19];
    float* out = (float*)d_out;

    const int* src = ei;
    const int* dst = ei + EE;

    void* degp = nullptr; cudaGetSymbolAddress(&degp, g_deg);
    void* curp = nullptr; cudaGetSymbolAddress(&curp, g_cur);
    cudaMemsetAsync(degp, 0, NN * sizeof(int));
    cudaMemsetAsync(curp, 0, NN * sizeof(int));
    k_count<<<EE / 256, 256>>>(dst);
    k_gtot<<<GG, 128>>>();
    k_gscan<<<1, GG>>>();
    k_noff<<<GG, 128>>>();
    k_scatter<<<EE / 256, 256>>>(src, dst);

    static_assert(sizeof(SmemD) <= 232448, "smem too large");
    cudaFuncSetAttribute(k_main, cudaFuncAttributeMaxDynamicSharedMemorySize,
                         (int)sizeof(SmemD));
    k_main<<<GG, 512, sizeof(SmemD)>>>(z, zt, W0, b0, W1, b1, W2, b2, W3, b3,
                                       c1w, c1b, c2w, c2b, l1w, l1b, l2w, l2b, out);
}